// round 7
// baseline (speedup 1.0000x reference)
#include <cuda_runtime.h>
#include <math.h>

// Problem constants (fixed by setup_inputs)
#define B 4
#define H 256
#define W 256
#define NPTS 256
#define HW (H*W)
#define NSTEPS 50
#define STEPSZ 0.1f
#define ALPHA 0.01f
#define BETA 0.005f
#define DMAX 15.0f
#define EXTGRADFAC 10.0f
// filter: stdev=2 -> r=6 -> 13 taps

// ---------------- device scratch (static allocation: allowed) ----------------
__device__ float2 g_gimg [B*HW];   // interleaved {fy,fx} per pixel
__device__ float2 g_gimgW[B*HW];
__device__ float4 g_nodes[B*NPTS]; // {y, x, w, pad}
__device__ float  g_part[256];
__device__ int    g_cnt = 0;       // last-block counter (self-resetting)

__device__ __forceinline__ float sqrt_approx(float q) {
    float r;
    asm("sqrt.approx.f32 %0, %1;" : "=f"(r) : "f"(q));
    return r;   // exact 0 at q == 0
}

// 13-tap Gaussian / derivative-of-Gaussian filter into shared mem.
// Matches the numpy float32 recipe: g = exp(-x^2/8); g /= sum(g); dg = -x/4 * g.
__device__ __forceinline__ void make_filter(float* g, float* dg, int tid) {
    if (tid < 13) {
        float xv = (float)(tid - 6);
        g[tid] = expf(-xv * xv * 0.125f);
    }
    __syncthreads();
    if (tid == 0) {
        float s = 0.f;
        #pragma unroll
        for (int i = 0; i < 13; i++) s += g[i];
        #pragma unroll
        for (int i = 0; i < 13; i++) {
            g[i]  = g[i] / s;
            dg[i] = -(float)(i - 6) * 0.25f * g[i];
        }
    }
    __syncthreads();
}

// ---------------- fused separable conv (both passes, one kernel) ------------
// Grid (8, 8, B): 32x32 output tile per block, 256 threads.
// Stage pred (44x44 with 6-px halo, zero-padded 'SAME'), horizontal conv into
// a float4 buffer (44 rows x 32 cols: {p*g, p*dg, |p|*g, |p|*dg}), then
// vertical conv producing both gradient images. ~30.6 KB static smem.
#define TS 32              // output tile size
#define HS (TS + 12)       // staged size with halo (44)
#define SPP (HS + 1)       // sp row pitch (45, pad to dodge conflicts)

__global__ void conv_fused(const float* __restrict__ pred) {
    __shared__ float g[13], dg[13];
    __shared__ float  sp[HS * SPP];     // 44*45*4  = 7.9 KB
    __shared__ float4 hc[HS * TS];      // 44*32*16 = 22.5 KB
    const int tid = threadIdx.x;
    const int b  = blockIdx.z;
    const int x0 = blockIdx.x * TS;
    const int y0 = blockIdx.y * TS;

    make_filter(g, dg, tid);

    // Phase A: stage pred tile + halo, zero outside the image ('SAME' pad)
    for (int idx = tid; idx < HS * HS; idx += 256) {
        int r = idx / HS, c = idx % HS;
        int gy = y0 + r - 6, gx = x0 + c - 6;
        float v = 0.f;
        if (gy >= 0 && gy < H && gx >= 0 && gx < W)
            v = __ldg(&pred[b * HW + gy * W + gx]);
        sp[r * SPP + c] = v;
    }
    __syncthreads();

    // Phase B: horizontal conv for all 44 rows x 32 output cols
    for (int idx = tid; idx < HS * TS; idx += 256) {
        int r = idx >> 5, c = idx & (TS - 1);
        const float* row = sp + r * SPP + c;   // taps at row[0..12]
        float ag = 0.f, adg = 0.f, bg = 0.f, bdg = 0.f;
        #pragma unroll
        for (int j = 0; j < 13; j++) {
            float p = row[j];
            float a = fabsf(p);
            ag  = fmaf(p, g[j],  ag);
            adg = fmaf(p, dg[j], adg);
            bg  = fmaf(a, g[j],  bg);
            bdg = fmaf(a, dg[j], bdg);
        }
        hc[idx] = make_float4(ag, adg, bg, bdg);
    }
    __syncthreads();

    // Phase C: vertical conv, 4 output pixels per thread
    for (int idx = tid; idx < TS * TS; idx += 256) {
        int r = idx >> 5, c = idx & (TS - 1);
        float o0 = 0.f, o1 = 0.f, o2 = 0.f, o3 = 0.f;
        #pragma unroll
        for (int i = 0; i < 13; i++) {
            float4 h = hc[(r + i) * TS + c];
            o0 = fmaf(h.x, dg[i], o0);   // fy of gimg  (dg_y * g_x)
            o1 = fmaf(h.y, g[i],  o1);   // fx of gimg  (g_y * dg_x)
            o2 = fmaf(h.z, dg[i], o2);   // fy of gimgW
            o3 = fmaf(h.w, g[i],  o3);   // fx of gimgW
        }
        const int o = b * HW + (y0 + r) * W + (x0 + c);
        g_gimg [o] = make_float2(o0 * EXTGRADFAC, o1 * EXTGRADFAC);
        g_gimgW[o] = make_float2(o2 * EXTGRADFAC, o3 * EXTGRADFAC);
    }
}

// ---------------- bilinear samplers ----------------
__device__ __forceinline__ void bilin2(const float2* __restrict__ img,
                                       float y, float x, float& r0, float& r1) {
    y = fminf(fmaxf(y, 0.f), 254.999f);
    x = fminf(fmaxf(x, 0.f), 254.999f);
    float fy = floorf(y), fx = floorf(x);
    int y0 = (int)fy, x0 = (int)fx;
    float ty = y - fy, tx = x - fx;
    float w00 = (1.f - ty) * (1.f - tx);
    float w01 = (1.f - ty) * tx;
    float w10 = ty * (1.f - tx);
    float w11 = ty * tx;
    int i = y0 * W + x0;
    float2 v00 = __ldg(img + i),     v01 = __ldg(img + i + 1);
    float2 v10 = __ldg(img + i + W), v11 = __ldg(img + i + W + 1);
    r0 = v00.x * w00 + v01.x * w01 + v10.x * w10 + v11.x * w11;
    r1 = v00.y * w00 + v01.y * w01 + v10.y * w10 + v11.y * w11;
}

// Sample both images at the same point: 8 concurrent LDG.64, shared index math.
__device__ __forceinline__ void bilin2_pair(const float2* __restrict__ ga,
                                            const float2* __restrict__ gb,
                                            float y, float x,
                                            float& a0, float& a1,
                                            float& b0, float& b1) {
    y = fminf(fmaxf(y, 0.f), 254.999f);
    x = fminf(fmaxf(x, 0.f), 254.999f);
    float fy = floorf(y), fx = floorf(x);
    int y0 = (int)fy, x0 = (int)fx;
    float ty = y - fy, tx = x - fx;
    float w00 = (1.f - ty) * (1.f - tx);
    float w01 = (1.f - ty) * tx;
    float w10 = ty * (1.f - tx);
    float w11 = ty * tx;
    int i = y0 * W + x0;
    float2 p00 = __ldg(ga + i),     p01 = __ldg(ga + i + 1);
    float2 p10 = __ldg(ga + i + W), p11 = __ldg(ga + i + W + 1);
    float2 q00 = __ldg(gb + i),     q01 = __ldg(gb + i + 1);
    float2 q10 = __ldg(gb + i + W), q11 = __ldg(gb + i + W + 1);
    a0 = p00.x * w00 + p01.x * w01 + p10.x * w10 + p11.x * w11;
    a1 = p00.y * w00 + p01.y * w01 + p10.y * w10 + p11.y * w11;
    b0 = q00.x * w00 + q01.x * w01 + q10.x * w10 + q11.x * w11;
    b1 = q00.y * w00 + q01.y * w01 + q10.y * w10 + q11.y * w11;
}

// ---------------- snake optimization: 4 blocks, 256 threads ----------------
// Ping-pong buffers, ONE barrier per step, software-pipelined gathers:
// the gimg sample for step s+1 is issued together with the gimgW sample of
// step s (both at the freshly-updated position) -> one gather latency per
// step; after step 0 the gathers are mostly L1 hits (positions drift slowly).
__global__ void snake(const float* __restrict__ node_pos,
                      const float* __restrict__ widths) {
    __shared__ float pyA[NPTS], pxA[NPTS], wdA[NPTS];
    __shared__ float pyB[NPTS], pxB[NPTS], wdB[NPTS];
    const int i = threadIdx.x;
    const int b = blockIdx.x;
    const float2* gi = g_gimg  + b * HW;
    const float2* gw = g_gimgW + b * HW;

    float y = node_pos[(b * NPTS + i) * 2 + 0];
    float x = node_pos[(b * NPTS + i) * 2 + 1];
    float wcur = widths[b * NPTS + i];
    pyA[i] = y; pxA[i] = x; wdA[i] = wcur;

    // prefetch force for step 0 (overlaps with the barrier)
    float f0, f1;
    bilin2(gi, y, x, f0, f1);
    __syncthreads();

    // clamped neighbor indices (edge replication, matching jnp concat stencil)
    const int im1 = (i == 0) ? 0 : i - 1;
    const int ip1 = (i == NPTS - 1) ? NPTS - 1 : i + 1;
    const int im1m = (im1 == 0) ? 0 : im1 - 1;
    const int im1p = (im1 == NPTS - 1) ? NPTS - 1 : im1 + 1;
    const int ip1m = (ip1 == 0) ? 0 : ip1 - 1;
    const int ip1p = (ip1 == NPTS - 1) ? NPTS - 1 : ip1 + 1;

    float *py = pyA, *px = pxA, *wd = wdA;
    float *qy = pyB, *qx = pxB, *qw = wdB;

    for (int step = 0; step < NSTEPS; step++) {
        // d2 at i, im1, ip1 evaluated directly (exact nested-_d2 semantics)
        float pm1y = py[im1], pp1y = py[ip1];
        float pm1x = px[im1], pp1x = px[ip1];
        float d2y  = pm1y - 2.f * y + pp1y;
        float d2x  = pm1x - 2.f * x + pp1x;
        float d2ym = py[im1m] - 2.f * pm1y + py[im1p];
        float d2xm = px[im1m] - 2.f * pm1x + px[im1p];
        float d2yp = py[ip1m] - 2.f * pp1y + py[ip1p];
        float d2xp = px[ip1m] - 2.f * pp1x + px[ip1p];
        float d4y = d2ym - 2.f * d2y + d2yp;
        float d4x = d2xm - 2.f * d2x + d2xp;

        float ny = fminf(fmaxf(y + STEPSZ * (ALPHA * d2y - BETA * d4y + f0), 0.f), (float)(H - 1));
        float nx = fminf(fmaxf(x + STEPSZ * (ALPHA * d2x - BETA * d4x + f1), 0.f), (float)(W - 1));

        // both gathers at the updated position: width force for THIS step and
        // snake force for the NEXT step, issued concurrently
        float w0, w1, nf0, nf1;
        bilin2_pair(gi, gw, ny, nx, nf0, nf1, w0, w1);

        float d2w = wd[im1] - 2.f * wcur + wd[ip1];
        float nw = fminf(fmaxf(wcur + STEPSZ * (ALPHA * d2w + (w0 + w1)), 0.f), DMAX);

        qy[i] = ny; qx[i] = nx; qw[i] = nw;
        __syncthreads();          // publishes q; no WAR (distinct buffers)
        float* t;
        t = py; py = qy; qy = t;
        t = px; px = qx; qx = t;
        t = wd; wd = qw; qw = t;
        y = ny; x = nx; wcur = nw; f0 = nf0; f1 = nf1;
    }

    g_nodes[b * NPTS + i] = make_float4(y, x, wcur, 0.f);
}

// ---------------- render + loss, tile-culled ----------------
// Grid (8, 8, B): one 32x32 pixel tile per block, 256 threads, 4 px/thread.
// A node can only influence the (DMAX-clipped) distance of a tile pixel if
// dist(pixel, node) < DMAX + w; culling against the tile center with radius
// margin 15.5*sqrt(2)=21.92 (+1.0 safety) keeps ~15-25 of 256 nodes. Any
// excluded node satisfies d - w >= DMAX for every tile pixel, so it cannot
// change clip(min, 0, DMAX). fminf over the compacted list is
// order-independent (finite floats). Last block does the final reduction.
__global__ void render_loss(const float* __restrict__ pred,
                            float* __restrict__ out) {
    __shared__ float4 kept[NPTS];
    __shared__ int scnt;
    __shared__ float wsum[8];
    __shared__ int slast;
    const int tid = threadIdx.x;
    const int b = blockIdx.z;
    const int x0 = blockIdx.x * 32;
    const int y0 = blockIdx.y * 32;

    if (tid == 0) scnt = 0;
    __syncthreads();

    // cull: one node per thread
    {
        float4 n = __ldg(&g_nodes[b * NPTS + tid]);
        const float cy = y0 + 15.5f, cx = x0 + 15.5f;
        float dy = cy - n.x, dx = cx - n.y;
        float d2c = fmaf(dy, dy, dx * dx);
        float thr = DMAX + n.z + 22.92f;
        if (d2c < thr * thr) {
            int k = atomicAdd(&scnt, 1);
            kept[k] = n;
        }
    }
    __syncthreads();
    const int m = scnt;

    float v = 0.f;
    #pragma unroll
    for (int q = 0; q < 4; q++) {
        const int idx = q * 256 + tid;
        const int pyi = y0 + (idx >> 5);
        const int pxi = x0 + (idx & 31);
        const float yy = (float)pyi;
        const float xx = (float)pxi;
        float pv = __ldg(&pred[b * HW + pyi * W + pxi]);

        float b0 = 3.0e38f, b1 = 3.0e38f;
        int k = 0;
        for (; k + 2 <= m; k += 2) {
            float4 n0 = kept[k], n1 = kept[k + 1];
            float dy0 = yy - n0.x, dx0 = xx - n0.y;
            float dy1 = yy - n1.x, dx1 = xx - n1.y;
            float q0 = fmaf(dy0, dy0, dx0 * dx0);
            float q1 = fmaf(dy1, dy1, dx1 * dx1);
            b0 = fminf(b0, sqrt_approx(q0) - n0.z);
            b1 = fminf(b1, sqrt_approx(q1) - n1.z);
        }
        if (k < m) {
            float4 n0 = kept[k];
            float dy0 = yy - n0.x, dx0 = xx - n0.y;
            float q0 = fmaf(dy0, dy0, dx0 * dx0);
            b0 = fminf(b0, sqrt_approx(q0) - n0.z);
        }
        float best = fminf(b0, b1);
        float dm = fminf(fmaxf(best, 0.f), DMAX);
        float e = pv - dm;
        v = fmaf(e, e, v);
    }

    // intra-block reduction (warp shuffle + shared)
    #pragma unroll
    for (int s = 16; s > 0; s >>= 1)
        v += __shfl_down_sync(0xFFFFFFFFu, v, s);
    if ((tid & 31) == 0) wsum[tid >> 5] = v;
    __syncthreads();
    if (tid == 0) {
        float s = 0.f;
        #pragma unroll
        for (int j = 0; j < 8; j++) s += wsum[j];
        g_part[b * 64 + blockIdx.y * 8 + blockIdx.x] = s;
        __threadfence();
        int t = atomicAdd(&g_cnt, 1);
        slast = (t == 8 * 8 * B - 1);
    }
    __syncthreads();

    // last block: final deterministic reduction over all 256 partials
    if (slast) {
        float s = g_part[tid];
        #pragma unroll
        for (int sft = 16; sft > 0; sft >>= 1)
            s += __shfl_down_sync(0xFFFFFFFFu, s, sft);
        if ((tid & 31) == 0) wsum[tid >> 5] = s;
        __syncthreads();
        if (tid == 0) {
            float tot = 0.f;
            #pragma unroll
            for (int j = 0; j < 8; j++) tot += wsum[j];
            out[0] = tot * (1.0f / (float)(B * HW));
            g_cnt = 0;   // reset for next graph replay
        }
    }
}

extern "C" void kernel_launch(void* const* d_in, const int* in_sizes, int n_in,
                              void* d_out, int out_size) {
    const float* pred     = (const float*)d_in[0];  // (4,1,256,256)
    const float* node_pos = (const float*)d_in[1];  // (4,256,2)
    const float* widths   = (const float*)d_in[2];  // (4,256)
    float* out = (float*)d_out;

    conv_fused<<<dim3(8, 8, B), 256>>>(pred);
    snake<<<B, NPTS>>>(node_pos, widths);
    render_loss<<<dim3(8, 8, B), 256>>>(pred, out);
}